// round 5
// baseline (speedup 1.0000x reference)
#include <cuda_runtime.h>

// LocSE fused kernel, round 5: pre-duplicated activation pairs in smem
// (LDS.64 replaces LDS + mov.b64 pack in the hot loops), zero-pad FMAs
// elided (25 instead of 27 per c-iter), layer-0 inputs via warp shuffles.
// Two-phase split (nrm tower + MLP half1 | ang tower + MLP half2) staging the
// pre-relu partial through d_out. 512 threads/block, 1 block/SM.

typedef unsigned long long ull;

__device__ __forceinline__ ull pk(float lo, float hi) {
    ull r; asm("mov.b64 %0, {%1, %2};" : "=l"(r) : "f"(lo), "f"(hi)); return r;
}
__device__ __forceinline__ void upk(ull v, float& lo, float& hi) {
    asm("mov.b64 {%0, %1}, %2;" : "=f"(lo), "=f"(hi) : "l"(v));
}
__device__ __forceinline__ ull fma2(ull a, ull b, ull c) {
#if __CUDA_ARCH__ >= 1000
    ull d; asm("fma.rn.f32x2 %0, %1, %2, %3;" : "=l"(d) : "l"(a), "l"(b), "l"(c));
    return d;
#else
    float ax, ay, bx, by, cx, cy;
    upk(a, ax, ay); upk(b, bx, by); upk(c, cx, cy);
    return pk(fmaf(ax, bx, cx), fmaf(ay, by, cy));
#endif
}
__device__ __forceinline__ ull dup2(float v) { return pk(v, v); }

// xb2 layout (per warp): 9 rows (logical padded rows 1..9) x 64 channels,
// each channel stored as a duplicated float pair -> row stride 128 floats.
// Lane writes channels {2*lane, 2*lane+1} as one float4 {v0,v0,v1,v1}.

// One residual conv layer: r = r + relu(conv1d(r + sum_c(r), W) + b)
__device__ __forceinline__ void conv_residual(ull r[9],
                                              const float* __restrict__ Wl,
                                              const float* __restrict__ bvec,
                                              float* __restrict__ xb2, int lane)
{
    float s[9];
#pragma unroll
    for (int t = 0; t < 9; t++) { float lo, hi; upk(r[t], lo, hi); s[t] = lo + hi; }
#pragma unroll
    for (int off = 16; off >= 1; off >>= 1) {
#pragma unroll
        for (int t = 0; t < 9; t++) s[t] += __shfl_xor_sync(0xffffffffu, s[t], off);
    }
    __syncwarp();
#pragma unroll
    for (int t = 0; t < 9; t++) {
        float lo, hi; upk(r[t], lo, hi);
        float4 st; st.x = lo + s[t]; st.y = st.x; st.z = hi + s[t]; st.w = st.z;
        *(float4*)(xb2 + t * 128 + 4 * lane) = st;
    }
    __syncwarp();

    ull acc[9];
    ull b2 = *(const ull*)(bvec + 2 * lane);
#pragma unroll
    for (int t = 0; t < 9; t++) acc[t] = b2;

#pragma unroll 2
    for (int c = 0; c < 64; c++) {
        ull xd[9];
#pragma unroll
        for (int j = 0; j < 9; j++) xd[j] = *(const ull*)(xb2 + j * 128 + 2 * c);
#pragma unroll
        for (int k = 0; k < 3; k++) {
            ull wk = *(const ull*)(Wl + (k * 64 + c) * 64 + 2 * lane);
#pragma unroll
            for (int t = 0; t < 9; t++) {
                int j = t + k - 1;              // storage row of padded row t+k
                if (j >= 0 && j <= 8)           // compile-time: skips zero pads
                    acc[t] = fma2(xd[j], wk, acc[t]);
            }
        }
    }
#pragma unroll
    for (int t = 0; t < 9; t++) {
        float lo, hi; upk(acc[t], lo, hi);
        lo = fmaxf(lo, 0.f); hi = fmaxf(hi, 0.f);
        float rl, rh; upk(r[t], rl, rh);
        r[t] = pk(rl + lo, rh + hi);
    }
}

// am += x(9x64) @ mws(64x64); x read from duplicated-pair buffer
__device__ __forceinline__ void mlp_pass(ull am[9], const float* __restrict__ xb2,
                                         const float* __restrict__ mws, int lane)
{
#pragma unroll 4
    for (int c = 0; c < 64; c++) {
        ull w = *(const ull*)(mws + c * 64 + 2 * lane);
        ull xd[9];
#pragma unroll
        for (int t = 0; t < 9; t++) xd[t] = *(const ull*)(xb2 + t * 128 + 2 * c);
#pragma unroll
        for (int t = 0; t < 9; t++) am[t] = fma2(xd[t], w, am[t]);
    }
}

// stash post-relu activations r into the duplicated-pair buffer
__device__ __forceinline__ void stash_r(const ull r[9], float* __restrict__ xb2, int lane)
{
    __syncwarp();
#pragma unroll
    for (int t = 0; t < 9; t++) {
        float lo, hi; upk(r[t], lo, hi);
        float4 st; st.x = lo; st.y = lo; st.z = hi; st.w = hi;
        *(float4*)(xb2 + t * 128 + 4 * lane) = st;
    }
    __syncwarp();
}

// ---------------------------------------------------------------------------
// Kernel 1: nrm tower + MLP half 1 -> out ch[0..63] (pre-relu) + feats copy
// ---------------------------------------------------------------------------
__global__ void __launch_bounds__(512, 1)
locse_k1(const float* __restrict__ pc, const float* __restrict__ feats,
         const float* __restrict__ nw0, const float* __restrict__ nb0,
         const float* __restrict__ nw1, const float* __restrict__ nb1,
         const float* __restrict__ nw2, const float* __restrict__ nb2,
         const float* __restrict__ mw, const float* __restrict__ mb,
         float* __restrict__ out, int ngroups)
{
    extern __shared__ float sm[];
    float* W   = sm;            // 2 * 12288 : [nrm_w1, nrm_w2]
    float* w0n = W + 24576;     // 192
    float* bia = w0n + 192;     // 192 : [nb0 nb1 nb2]
    float* mbs = bia + 192;     // 64
    float* mws = mbs + 64;      // 4096 : mlp_w rows 0..63
    float* xba = mws + 4096;    // 16 warps * 1152 (9 rows x 64 dup-pairs)

    const int tid = threadIdx.x;
    for (int i = tid; i < 12288; i += 512) {
        W[i]         = nw1[i];
        W[12288 + i] = nw2[i];
    }
    for (int i = tid; i < 4096; i += 512) mws[i] = mw[i];
    if (tid < 192) w0n[tid] = nw0[tid];
    if (tid < 64) {
        bia[tid]       = nb0[tid];
        bia[64 + tid]  = nb1[tid];
        bia[128 + tid] = nb2[tid];
        mbs[tid]       = mb[tid];
    }
    const int warp = tid >> 5, lane = tid & 31;
    float* xb2 = xba + warp * 1152;
    __syncthreads();

    const int stride = gridDim.x * 16;
    for (int g = blockIdx.x * 16 + warp; g < ngroups; g += stride) {
        // prep: lane s (<9) handles point s
        float4 p = make_float4(0.f, 0.f, 0.f, 0.f);
        if (lane < 9) p = *(const float4*)(pc + (size_t)g * 36 + lane * 4);
        float ccx = __shfl_sync(0xffffffffu, p.x, 0);
        float val = 2.0f * (ccx - p.x);         // x + sum_c(x), cin=1 -> 2*dx

        ull xd0[9];
#pragma unroll
        for (int j = 0; j < 9; j++) xd0[j] = dup2(__shfl_sync(0xffffffffu, val, j));

        ull r[9];
        {
            ull b2 = *(const ull*)(bia + 2 * lane);
            ull acc[9];
#pragma unroll
            for (int t = 0; t < 9; t++) acc[t] = b2;
#pragma unroll
            for (int k = 0; k < 3; k++) {
                ull wk = *(const ull*)(w0n + k * 64 + 2 * lane);
#pragma unroll
                for (int t = 0; t < 9; t++) {
                    int j = t + k - 1;
                    if (j >= 0 && j <= 8) acc[t] = fma2(xd0[j], wk, acc[t]);
                }
            }
#pragma unroll
            for (int t = 0; t < 9; t++) {
                float lo, hi; upk(acc[t], lo, hi);
                r[t] = pk(fmaxf(lo, 0.f), fmaxf(hi, 0.f));
            }
        }
        conv_residual(r, W,         bia + 64,  xb2, lane);
        conv_residual(r, W + 12288, bia + 128, xb2, lane);

        stash_r(r, xb2, lane);
        ull am[9];
        {
            ull b2 = *(const ull*)(mbs + 2 * lane);
#pragma unroll
            for (int t = 0; t < 9; t++) am[t] = b2;
        }
        mlp_pass(am, xb2, mws, lane);

        // stage pre-relu partial into out ch[0..63]; feats into ch[64..127]
        float* og = out + (size_t)g * 1152;
#pragma unroll
        for (int t = 0; t < 9; t++) *(ull*)(og + t * 128 + 2 * lane) = am[t];

        const float4* f4 = (const float4*)(feats + (size_t)g * 576);
        float4* o4 = (float4*)og;
        for (int i = lane; i < 144; i += 32) {
            int row = i >> 4, col = i & 15;
            o4[row * 32 + 16 + col] = f4[i];
        }
    }
}

// ---------------------------------------------------------------------------
// Kernel 2: ang tower + MLP half 2; out ch[0..63] += , then relu
// ---------------------------------------------------------------------------
__global__ void __launch_bounds__(512, 1)
locse_k2(const float* __restrict__ pc,
         const float* __restrict__ aw0, const float* __restrict__ ab0,
         const float* __restrict__ aw1, const float* __restrict__ ab1,
         const float* __restrict__ aw2, const float* __restrict__ ab2,
         const float* __restrict__ mw,
         float* __restrict__ out, int ngroups)
{
    extern __shared__ float sm[];
    float* W   = sm;            // 2 * 12288 : [ang_w1, ang_w2]
    float* w0a = W + 24576;     // 576
    float* bia = w0a + 576;     // 192 : [ab0 ab1 ab2]
    float* mws = bia + 192;     // 4096 : mlp_w rows 64..127
    float* xba = mws + 4096;    // 16 warps * 1152

    const int tid = threadIdx.x;
    for (int i = tid; i < 12288; i += 512) {
        W[i]         = aw1[i];
        W[12288 + i] = aw2[i];
    }
    for (int i = tid; i < 4096; i += 512) mws[i] = mw[4096 + i];
    for (int i = tid; i < 576; i += 512) w0a[i] = aw0[i];
    if (tid < 64) {
        bia[tid]       = ab0[tid];
        bia[64 + tid]  = ab1[tid];
        bia[128 + tid] = ab2[tid];
    }
    const int warp = tid >> 5, lane = tid & 31;
    float* xb2 = xba + warp * 1152;
    __syncthreads();

    const int stride = gridDim.x * 16;
    for (int g = blockIdx.x * 16 + warp; g < ngroups; g += stride) {
        // prep: lane s (<9) handles point s
        float4 p = make_float4(0.f, 0.f, 0.f, 0.f);
        if (lane < 9) p = *(const float4*)(pc + (size_t)g * 36 + lane * 4);
        float ccx = __shfl_sync(0xffffffffu, p.x, 0);
        float ccy = __shfl_sync(0xffffffffu, p.y, 0);
        float ccz = __shfl_sync(0xffffffffu, p.z, 0);
        float ccw = __shfl_sync(0xffffffffu, p.w, 0);

        float dx = ccx - p.x, dy = ccy - p.y;
        float s1 = p.x * p.x + p.y * p.y;
        float nrmv = (s1 > 0.f) ? sqrtf(s1) : 0.f;
        float s2 = dx * dx + dy * dy;
        float dn = (s2 > 0.f) ? sqrtf(s2) : 0.f;
        float s3 = ccx * ccx + ccy * ccy + ccz * ccz + ccw * ccw;
        float cn = (s3 > 0.f) ? sqrtf(s3) : 0.f;
        float num = dx * ccz + dy * ccw;
        float den = dn * cn + 1e-8f;
        float ang = 1.0f - fabsf(num / den);
        float ssum = dy + nrmv + ang;
        float av[3]; av[0] = dy + ssum; av[1] = nrmv + ssum; av[2] = ang + ssum;

        ull r[9];
        {
            ull b2 = *(const ull*)(bia + 2 * lane);
            ull acc[9];
#pragma unroll
            for (int t = 0; t < 9; t++) acc[t] = b2;
#pragma unroll
            for (int c = 0; c < 3; c++) {
                ull xd0[9];
#pragma unroll
                for (int j = 0; j < 9; j++) xd0[j] = dup2(__shfl_sync(0xffffffffu, av[c], j));
#pragma unroll
                for (int k = 0; k < 3; k++) {
                    ull wk = *(const ull*)(w0a + (k * 3 + c) * 64 + 2 * lane);
#pragma unroll
                    for (int t = 0; t < 9; t++) {
                        int j = t + k - 1;
                        if (j >= 0 && j <= 8) acc[t] = fma2(xd0[j], wk, acc[t]);
                    }
                }
            }
#pragma unroll
            for (int t = 0; t < 9; t++) {
                float lo, hi; upk(acc[t], lo, hi);
                r[t] = pk(fmaxf(lo, 0.f), fmaxf(hi, 0.f));
            }
        }
        conv_residual(r, W,         bia + 64,  xb2, lane);
        conv_residual(r, W + 12288, bia + 128, xb2, lane);

        stash_r(r, xb2, lane);

        float* og = out + (size_t)g * 1152;
        ull am[9];
#pragma unroll
        for (int t = 0; t < 9; t++) am[t] = *(const ull*)(og + t * 128 + 2 * lane);
        mlp_pass(am, xb2, mws, lane);

#pragma unroll
        for (int t = 0; t < 9; t++) {
            float lo, hi; upk(am[t], lo, hi);
            *(ull*)(og + t * 128 + 2 * lane) = pk(fmaxf(lo, 0.f), fmaxf(hi, 0.f));
        }
    }
}

extern "C" void kernel_launch(void* const* d_in, const int* in_sizes, int n_in,
                              void* d_out, int out_size)
{
    const float* pc    = (const float*)d_in[0];
    const float* feats = (const float*)d_in[1];
    // 2..13 = pos_* / rel_* (dead in the reference: pos_e/rel_e are discarded)
    const float* nw0 = (const float*)d_in[14];
    const float* nb0 = (const float*)d_in[15];
    const float* nw1 = (const float*)d_in[16];
    const float* nb1 = (const float*)d_in[17];
    const float* nw2 = (const float*)d_in[18];
    const float* nb2 = (const float*)d_in[19];
    const float* aw0 = (const float*)d_in[20];
    const float* ab0 = (const float*)d_in[21];
    const float* aw1 = (const float*)d_in[22];
    const float* ab1 = (const float*)d_in[23];
    const float* aw2 = (const float*)d_in[24];
    const float* ab2 = (const float*)d_in[25];
    const float* mw  = (const float*)d_in[26];
    const float* mb  = (const float*)d_in[27];

    const int ngroups = in_sizes[0] / 36;   // B*N groups of S=9 points x 4

    const int smem1 = (24576 + 192 + 192 + 64 + 4096 + 16 * 1152) * 4;  // 190208
    const int smem2 = (24576 + 576 + 192 + 4096 + 16 * 1152) * 4;       // 191488

    cudaFuncSetAttribute(locse_k1, cudaFuncAttributeMaxDynamicSharedMemorySize, smem1);
    cudaFuncSetAttribute(locse_k2, cudaFuncAttributeMaxDynamicSharedMemorySize, smem2);

    locse_k1<<<152, 512, smem1>>>(pc, feats, nw0, nb0, nw1, nb1, nw2, nb2,
                                  mw, mb, (float*)d_out, ngroups);
    locse_k2<<<152, 512, smem2>>>(pc, aw0, ab0, aw1, ab1, aw2, ab2,
                                  mw, (float*)d_out, ngroups);
}